// round 2
// baseline (speedup 1.0000x reference)
#include <cuda_runtime.h>
#include <cstdint>

// Problem constants (shapes fixed by dataset; guarded anyway).
#define N_NODES_MAX 100000
#define N_EDGES_MAX 1600000
#define IN_F  256
#define OUT_F 128

// ---------------- device scratch (__device__ globals are sanctioned) -------
__device__ float g_h[(size_t)N_NODES_MAX * OUT_F];     // 51.2 MB: h = x @ w
__device__ int   g_counts[N_NODES_MAX];                // per-dst edge count
__device__ int   g_rowstart[N_NODES_MAX];              // CSR row offsets
__device__ int   g_cursor[N_NODES_MAX];                // fill cursors
__device__ int   g_sorted_src[N_EDGES_MAX];            // src grouped by dst
__device__ float g_sorted_w[N_EDGES_MAX];              // weight grouped by dst

__device__ __forceinline__ int clamp_idx(int v, int n) {
    // defensive: keep any mis-decoded index in-range (wrong answer >> trap)
    v = v < 0 ? 0 : v;
    return v >= n ? n - 1 : v;
}

// ---------------- 1) SGEMM: g_h = x @ w  (M x 256) @ (256 x 128) -----------
// BM=128, BN=128(=OUT_F), BK=8, TM=TN=8, 256 threads/block.
__global__ __launch_bounds__(256) void gemm_kernel(
    const float* __restrict__ x, const float* __restrict__ w, int M)
{
    __shared__ float As[8][128];
    __shared__ float Bs[8][128];

    const int tid = threadIdx.x;
    const int block_row = blockIdx.x * 128;

    const int ty = tid >> 4;         // 0..15
    const int tx = tid & 15;         // 0..15

    const int ar = tid >> 1;         // A-load: row 0..127
    const int ac = (tid & 1) * 4;    //         4 floats along K
    const int br = tid >> 5;         // B-load: k-row 0..7
    const int bc = (tid & 31) * 4;   //         4 floats along N

    float acc[8][8];
#pragma unroll
    for (int i = 0; i < 8; i++)
#pragma unroll
        for (int j = 0; j < 8; j++) acc[i][j] = 0.0f;

    const int arow = block_row + ar;
    const bool arow_ok = (arow < M);
    const float* a_ptr = x + (size_t)arow * IN_F + ac;

    for (int kt = 0; kt < IN_F / 8; kt++) {
        const int kbase = kt * 8;
        float4 av = make_float4(0.f, 0.f, 0.f, 0.f);
        if (arow_ok) av = *reinterpret_cast<const float4*>(a_ptr + kbase);
        As[ac + 0][ar] = av.x;
        As[ac + 1][ar] = av.y;
        As[ac + 2][ar] = av.z;
        As[ac + 3][ar] = av.w;
        float4 bv = *reinterpret_cast<const float4*>(w + (size_t)(kbase + br) * OUT_F + bc);
        *reinterpret_cast<float4*>(&Bs[br][bc]) = bv;
        __syncthreads();

#pragma unroll
        for (int k = 0; k < 8; k++) {
            float4 a0 = *reinterpret_cast<float4*>(&As[k][ty * 8]);
            float4 a1 = *reinterpret_cast<float4*>(&As[k][ty * 8 + 4]);
            float4 b0 = *reinterpret_cast<float4*>(&Bs[k][tx * 8]);
            float4 b1 = *reinterpret_cast<float4*>(&Bs[k][tx * 8 + 4]);
            float ra[8] = {a0.x, a0.y, a0.z, a0.w, a1.x, a1.y, a1.z, a1.w};
            float rb[8] = {b0.x, b0.y, b0.z, b0.w, b1.x, b1.y, b1.z, b1.w};
#pragma unroll
            for (int i = 0; i < 8; i++)
#pragma unroll
                for (int j = 0; j < 8; j++) acc[i][j] += ra[i] * rb[j];
        }
        __syncthreads();
    }

#pragma unroll
    for (int i = 0; i < 8; i++) {
        const int row = block_row + ty * 8 + i;
        if (row < M) {
            float* o = g_h + (size_t)row * OUT_F + tx * 8;
            *reinterpret_cast<float4*>(o)     = make_float4(acc[i][0], acc[i][1], acc[i][2], acc[i][3]);
            *reinterpret_cast<float4*>(o + 4) = make_float4(acc[i][4], acc[i][5], acc[i][6], acc[i][7]);
        }
    }
}

// ---------------- 2) CSR build: zero / histogram / scan / fill -------------
__global__ void zero_counts_kernel(int n)
{
    int i = blockIdx.x * blockDim.x + threadIdx.x;
    if (i < n) g_counts[i] = 0;
}

__global__ void hist_kernel(const int* __restrict__ edst, int E, int n_nodes)
{
    int e = blockIdx.x * blockDim.x + threadIdx.x;
    if (e < E) {
        int d = clamp_idx(edst[e], n_nodes);
        atomicAdd(&g_counts[d], 1);
    }
}

// single block, 1024 threads: exclusive scan of g_counts -> g_rowstart/g_cursor
__global__ __launch_bounds__(1024) void scan_kernel(int n)
{
    __shared__ int sm[1024];
    const int t = threadIdx.x;
    const int chunk = (n + 1023) / 1024;
    const int beg = t * chunk;
    const int end = min(beg + chunk, n);

    int s = 0;
    for (int i = beg; i < end; i++) s += g_counts[i];
    sm[t] = s;
    __syncthreads();
    for (int off = 1; off < 1024; off <<= 1) {
        int v = (t >= off) ? sm[t - off] : 0;
        __syncthreads();
        sm[t] += v;
        __syncthreads();
    }
    int run = (t == 0) ? 0 : sm[t - 1];
    for (int i = beg; i < end; i++) {
        g_rowstart[i] = run;
        g_cursor[i]   = run;
        run += g_counts[i];
    }
}

__global__ void fill_kernel(const int* __restrict__ esrc,
                            const int* __restrict__ edst,
                            const float* __restrict__ ew, int E, int n_nodes)
{
    int e = blockIdx.x * blockDim.x + threadIdx.x;
    if (e < E) {
        int d = clamp_idx(edst[e], n_nodes);
        int pos = atomicAdd(&g_cursor[d], 1);
        if (pos >= 0 && pos < N_EDGES_MAX) {
            g_sorted_src[pos] = clamp_idx(esrc[e], n_nodes);
            g_sorted_w[pos]   = ew[e];
        }
    }
}

// ---------------- 3) gather: one warp per node, atomic-free ----------------
__global__ __launch_bounds__(256) void gather_kernel(
    const float* __restrict__ b, float* __restrict__ out, int n_nodes)
{
    const int gtid = blockIdx.x * blockDim.x + threadIdx.x;
    const int node = gtid >> 5;
    const int lane = gtid & 31;
    if (node >= n_nodes) return;

    const int start = g_rowstart[node];
    const int cnt   = g_counts[node];

    float4 acc = make_float4(0.f, 0.f, 0.f, 0.f);
    for (int j = 0; j < cnt; j++) {
        const int   s  = g_sorted_src[start + j];     // uniform across warp
        const float wt = g_sorted_w[start + j];
        const float4 v = *reinterpret_cast<const float4*>(
            g_h + (size_t)s * OUT_F + lane * 4);
        acc.x += wt * v.x;
        acc.y += wt * v.y;
        acc.z += wt * v.z;
        acc.w += wt * v.w;
    }
    const float4 bb = reinterpret_cast<const float4*>(b)[lane];
    acc.x += bb.x; acc.y += bb.y; acc.z += bb.z; acc.w += bb.w;
    reinterpret_cast<float4*>(out)[(size_t)node * 32 + lane] = acc;
}

// ---------------------------- launch ---------------------------------------
extern "C" void kernel_launch(void* const* d_in, const int* in_sizes, int n_in,
                              void* d_out, int out_size)
{
    const float* x    = (const float*)d_in[0];
    const int*   esrc = (const int*)d_in[1];   // JAX x64 disabled -> int32
    const int*   edst = (const int*)d_in[2];
    const float* ew   = (const float*)d_in[3];
    const float* w    = (const float*)d_in[4];
    const float* b    = (const float*)d_in[5];
    float*       out  = (float*)d_out;

    const int M = in_sizes[0] / IN_F;   // 100000 nodes
    const int E = in_sizes[1];          // 1600000 edges

    gemm_kernel<<<(M + 127) / 128, 256>>>(x, w, M);
    zero_counts_kernel<<<(M + 255) / 256, 256>>>(M);
    hist_kernel<<<(E + 255) / 256, 256>>>(edst, E, M);
    scan_kernel<<<1, 1024>>>(M);
    fill_kernel<<<(E + 255) / 256, 256>>>(esrc, edst, ew, E, M);
    gather_kernel<<<((M * 32) + 255) / 256, 256>>>(b, out, M);
}

// round 3
// speedup vs baseline: 1.5142x; 1.5142x over previous
#include <cuda_runtime.h>
#include <cstdint>

#define N_NODES_MAX 100000
#define N_EDGES_MAX 1600000
#define IN_F  256
#define OUT_F 128
#define SCAN_CHUNK 1024
#define MAX_SCAN_BLOCKS ((N_NODES_MAX + SCAN_CHUNK - 1) / SCAN_CHUNK)   // 98

// ---------------- device scratch (__device__ globals are sanctioned) -------
__device__ float g_h[(size_t)N_NODES_MAX * OUT_F];     // 51.2 MB: h = x @ w
__device__ int   g_counts[N_NODES_MAX];
__device__ int   g_rowstart[N_NODES_MAX];
__device__ int   g_cursor[N_NODES_MAX];
__device__ int   g_sorted_src[N_EDGES_MAX];
__device__ float g_sorted_w[N_EDGES_MAX];
__device__ int   g_blocksums[MAX_SCAN_BLOCKS];
__device__ int   g_blockoffs[MAX_SCAN_BLOCKS];

__device__ __forceinline__ int clamp_idx(int v, int n) {
    v = v < 0 ? 0 : v;
    return v >= n ? n - 1 : v;
}

// ---------------- 1) SGEMM: g_h = x @ w  (M x 256) @ (256 x 128) -----------
__global__ __launch_bounds__(256) void gemm_kernel(
    const float* __restrict__ x, const float* __restrict__ w, int M)
{
    __shared__ float As[8][128];
    __shared__ float Bs[8][128];

    const int tid = threadIdx.x;
    const int block_row = blockIdx.x * 128;

    const int ty = tid >> 4;
    const int tx = tid & 15;

    const int ar = tid >> 1;
    const int ac = (tid & 1) * 4;
    const int br = tid >> 5;
    const int bc = (tid & 31) * 4;

    float acc[8][8];
#pragma unroll
    for (int i = 0; i < 8; i++)
#pragma unroll
        for (int j = 0; j < 8; j++) acc[i][j] = 0.0f;

    const int arow = block_row + ar;
    const bool arow_ok = (arow < M);
    const float* a_ptr = x + (size_t)arow * IN_F + ac;

    for (int kt = 0; kt < IN_F / 8; kt++) {
        const int kbase = kt * 8;
        float4 av = make_float4(0.f, 0.f, 0.f, 0.f);
        if (arow_ok) av = *reinterpret_cast<const float4*>(a_ptr + kbase);
        As[ac + 0][ar] = av.x;
        As[ac + 1][ar] = av.y;
        As[ac + 2][ar] = av.z;
        As[ac + 3][ar] = av.w;
        float4 bv = *reinterpret_cast<const float4*>(w + (size_t)(kbase + br) * OUT_F + bc);
        *reinterpret_cast<float4*>(&Bs[br][bc]) = bv;
        __syncthreads();

#pragma unroll
        for (int k = 0; k < 8; k++) {
            float4 a0 = *reinterpret_cast<float4*>(&As[k][ty * 8]);
            float4 a1 = *reinterpret_cast<float4*>(&As[k][ty * 8 + 4]);
            float4 b0 = *reinterpret_cast<float4*>(&Bs[k][tx * 8]);
            float4 b1 = *reinterpret_cast<float4*>(&Bs[k][tx * 8 + 4]);
            float ra[8] = {a0.x, a0.y, a0.z, a0.w, a1.x, a1.y, a1.z, a1.w};
            float rb[8] = {b0.x, b0.y, b0.z, b0.w, b1.x, b1.y, b1.z, b1.w};
#pragma unroll
            for (int i = 0; i < 8; i++)
#pragma unroll
                for (int j = 0; j < 8; j++) acc[i][j] += ra[i] * rb[j];
        }
        __syncthreads();
    }

#pragma unroll
    for (int i = 0; i < 8; i++) {
        const int row = block_row + ty * 8 + i;
        if (row < M) {
            float* o = g_h + (size_t)row * OUT_F + tx * 8;
            *reinterpret_cast<float4*>(o)     = make_float4(acc[i][0], acc[i][1], acc[i][2], acc[i][3]);
            *reinterpret_cast<float4*>(o + 4) = make_float4(acc[i][4], acc[i][5], acc[i][6], acc[i][7]);
        }
    }
}

// ---------------- 2) CSR build -----------------------------------------
__global__ void zero_counts_kernel(int n)
{
    int i = blockIdx.x * blockDim.x + threadIdx.x;
    if (i < n) g_counts[i] = 0;
}

__global__ void hist_kernel(const int* __restrict__ edst, int E, int n_nodes)
{
    int e = blockIdx.x * blockDim.x + threadIdx.x;
    if (e < E) {
        int d = clamp_idx(edst[e], n_nodes);
        atomicAdd(&g_counts[d], 1);
    }
}

// --- parallel exclusive scan over g_counts (3 passes) ---
// pass 1: per-block sums (1024 counts per block, 1024 threads)
__global__ __launch_bounds__(1024) void scan_pass1(int n)
{
    __shared__ int warp_sums[32];
    const int tid = threadIdx.x;
    const int i = blockIdx.x * SCAN_CHUNK + tid;
    int v = (i < n) ? g_counts[i] : 0;
    // warp reduce
    int s = v;
#pragma unroll
    for (int off = 16; off > 0; off >>= 1) s += __shfl_down_sync(0xffffffffu, s, off);
    if ((tid & 31) == 0) warp_sums[tid >> 5] = s;
    __syncthreads();
    if (tid < 32) {
        int t = warp_sums[tid];
#pragma unroll
        for (int off = 16; off > 0; off >>= 1) t += __shfl_down_sync(0xffffffffu, t, off);
        if (tid == 0) g_blocksums[blockIdx.x] = t;
    }
}

// pass 2: exclusive scan of block sums (single block, nblocks <= 128)
__global__ __launch_bounds__(128) void scan_pass2(int nblocks)
{
    const int tid = threadIdx.x;
    int v = (tid < nblocks) ? g_blocksums[tid] : 0;
    // inclusive scan across 128 threads via shfl (4 warps)
    int x = v;
#pragma unroll
    for (int off = 1; off < 32; off <<= 1) {
        int y = __shfl_up_sync(0xffffffffu, x, off);
        if ((tid & 31) >= off) x += y;
    }
    __shared__ int ws[4];
    if ((tid & 31) == 31) ws[tid >> 5] = x;
    __syncthreads();
    int add = 0;
    for (int wlt = 0; wlt < (tid >> 5); wlt++) add += ws[wlt];
    int incl = x + add;
    if (tid < nblocks) g_blockoffs[tid] = incl - v;   // exclusive
}

// pass 3: per-block exclusive scan + block offset -> rowstart/cursor
__global__ __launch_bounds__(1024) void scan_pass3(int n)
{
    __shared__ int warp_sums[32];
    const int tid = threadIdx.x;
    const int i = blockIdx.x * SCAN_CHUNK + tid;
    int v = (i < n) ? g_counts[i] : 0;

    // intra-warp inclusive scan
    int x = v;
#pragma unroll
    for (int off = 1; off < 32; off <<= 1) {
        int y = __shfl_up_sync(0xffffffffu, x, off);
        if ((tid & 31) >= off) x += y;
    }
    if ((tid & 31) == 31) warp_sums[tid >> 5] = x;
    __syncthreads();
    // scan the 32 warp sums in warp 0
    if (tid < 32) {
        int t = warp_sums[tid];
#pragma unroll
        for (int off = 1; off < 32; off <<= 1) {
            int y = __shfl_up_sync(0xffffffffu, t, off);
            if (tid >= off) t += y;
        }
        warp_sums[tid] = t;   // inclusive warp-sum scan
    }
    __syncthreads();
    int warp_off = (tid >> 5) ? warp_sums[(tid >> 5) - 1] : 0;
    int excl = x - v + warp_off + g_blockoffs[blockIdx.x];
    if (i < n) {
        g_rowstart[i] = excl;
        g_cursor[i]   = excl;
    }
}

__global__ void fill_kernel(const int* __restrict__ esrc,
                            const int* __restrict__ edst,
                            const float* __restrict__ ew, int E, int n_nodes)
{
    int e = blockIdx.x * blockDim.x + threadIdx.x;
    if (e < E) {
        int d = clamp_idx(edst[e], n_nodes);
        int pos = atomicAdd(&g_cursor[d], 1);
        if (pos >= 0 && pos < N_EDGES_MAX) {
            g_sorted_src[pos] = clamp_idx(esrc[e], n_nodes);
            g_sorted_w[pos]   = ew[e];
        }
    }
}

// ---------------- 3) gather: one warp per node, atomic-free ----------------
__global__ __launch_bounds__(256) void gather_kernel(
    const float* __restrict__ b, float* __restrict__ out, int n_nodes)
{
    const int gtid = blockIdx.x * blockDim.x + threadIdx.x;
    const int node = gtid >> 5;
    const int lane = gtid & 31;
    if (node >= n_nodes) return;

    const int start = g_rowstart[node];
    const int cnt   = g_counts[node];

    float4 acc = make_float4(0.f, 0.f, 0.f, 0.f);
    for (int j = 0; j < cnt; j++) {
        const int   s  = g_sorted_src[start + j];
        const float wt = g_sorted_w[start + j];
        const float4 v = *reinterpret_cast<const float4*>(
            g_h + (size_t)s * OUT_F + lane * 4);
        acc.x += wt * v.x;
        acc.y += wt * v.y;
        acc.z += wt * v.z;
        acc.w += wt * v.w;
    }
    const float4 bb = reinterpret_cast<const float4*>(b)[lane];
    acc.x += bb.x; acc.y += bb.y; acc.z += bb.z; acc.w += bb.w;
    reinterpret_cast<float4*>(out)[(size_t)node * 32 + lane] = acc;
}

// ---------------------------- launch ---------------------------------------
extern "C" void kernel_launch(void* const* d_in, const int* in_sizes, int n_in,
                              void* d_out, int out_size)
{
    const float* x    = (const float*)d_in[0];
    const int*   esrc = (const int*)d_in[1];
    const int*   edst = (const int*)d_in[2];
    const float* ew   = (const float*)d_in[3];
    const float* w    = (const float*)d_in[4];
    const float* b    = (const float*)d_in[5];
    float*       out  = (float*)d_out;

    const int M = in_sizes[0] / IN_F;   // 100000
    const int E = in_sizes[1];          // 1600000
    const int nscan = (M + SCAN_CHUNK - 1) / SCAN_CHUNK;   // 98

    gemm_kernel<<<(M + 127) / 128, 256>>>(x, w, M);
    zero_counts_kernel<<<(M + 255) / 256, 256>>>(M);
    hist_kernel<<<(E + 255) / 256, 256>>>(edst, E, M);
    scan_pass1<<<nscan, 1024>>>(M);
    scan_pass2<<<1, 128>>>(nscan);
    scan_pass3<<<nscan, 1024>>>(M);
    fill_kernel<<<(E + 255) / 256, 256>>>(esrc, edst, ew, E, M);
    gather_kernel<<<((M * 32) + 255) / 256, 256>>>(b, out, M);
}